// round 1
// baseline (speedup 1.0000x reference)
#include <cuda_runtime.h>
#include <math.h>

#define B_ 512
#define S_ 200
#define H_ 512
#define A_ 32
#define M_ (B_*S_)          // 102400 rows
#define NEGV (-1e9f)

// ---------------- device scratch (no allocations allowed) ----------------
__device__ float g_moe[(M_ + 64) * H_];   // ~210MB: tanh(x@lin_w+b)+x, then LN'd in place
__device__ float g_w[M_];                 // attention logits -> tma softmax (in place)
__device__ float g_bij[M_ * A_];          // gates logits / routing logits
__device__ float g_cijt[M_ * A_];         // cij * tma per routing iter
__device__ float g_awT[H_ * A_];          // aspect_w transposed [k][a]
__device__ int   g_count[B_ * A_];        // top-1 scatter counts
__device__ float g_dummy_gates[M_ * A_];  // fallback targets if out_size is small
__device__ float g_dummy_mask[B_ * A_];

// ---------------- init ----------------
__global__ void zero_kernel() {
    int i = blockIdx.x * blockDim.x + threadIdx.x;
    if (i < M_) g_w[i] = 0.0f;
    if (i < B_ * A_) g_count[i] = 0;
}

__global__ void transpose_aw_kernel(const float* __restrict__ aw) {
    int i = blockIdx.x * blockDim.x + threadIdx.x;
    if (i < A_ * H_) {
        int a = i >> 9, k = i & 511;
        g_awT[k * A_ + a] = aw[i];
    }
}

// ---------------- tiled SGEMM 128x128x16, 8x8 per thread ----------------
// MODE 0: attention. A-load adds pos_emb; epilogue: leaky(acc+b1)*w2 reduced
//         over columns, atomicAdd into g_w[row].
// MODE 1: moe. epilogue: tanh(acc+lin_b)+item -> g_moe.
template <int MODE>
__launch_bounds__(256)
__global__ void sgemm_kernel(const float* __restrict__ Amat,
                             const float* __restrict__ Bmat,
                             const float* __restrict__ pos,
                             const float* __restrict__ bias,
                             const float* __restrict__ w2) {
    __shared__ float As[16][128];
    __shared__ float Bs[16][128];
    int tid = threadIdx.x;
    int tx = tid & 15, ty = tid >> 4;
    int row0 = blockIdx.y * 128;
    int n0 = blockIdx.x * 128;

    float acc[8][8];
#pragma unroll
    for (int i = 0; i < 8; i++)
#pragma unroll
        for (int j = 0; j < 8; j++) acc[i][j] = 0.0f;

    for (int k0 = 0; k0 < H_; k0 += 16) {
#pragma unroll
        for (int i = 0; i < 2; i++) {
            int ff = tid * 2 + i;
            int r = ff >> 2, cv = (ff & 3) * 4;
            int grow = row0 + r;
            float4 v = *(const float4*)&Amat[grow * H_ + k0 + cv];
            if (MODE == 0) {
                int s = grow % S_;
                float4 p = *(const float4*)&pos[s * H_ + k0 + cv];
                v.x += p.x; v.y += p.y; v.z += p.z; v.w += p.w;
            }
            As[cv + 0][r] = v.x; As[cv + 1][r] = v.y;
            As[cv + 2][r] = v.z; As[cv + 3][r] = v.w;
        }
#pragma unroll
        for (int i = 0; i < 2; i++) {
            int ff = tid * 2 + i;
            int r = ff >> 5, cv = (ff & 31) * 4;
            *(float4*)&Bs[r][cv] = *(const float4*)&Bmat[(k0 + r) * H_ + n0 + cv];
        }
        __syncthreads();
#pragma unroll
        for (int kk = 0; kk < 16; kk++) {
            float rm[8], rn[8];
            *(float4*)&rm[0] = *(float4*)&As[kk][ty * 8];
            *(float4*)&rm[4] = *(float4*)&As[kk][ty * 8 + 4];
            *(float4*)&rn[0] = *(float4*)&Bs[kk][tx * 8];
            *(float4*)&rn[4] = *(float4*)&Bs[kk][tx * 8 + 4];
#pragma unroll
            for (int i = 0; i < 8; i++)
#pragma unroll
                for (int j = 0; j < 8; j++) acc[i][j] += rm[i] * rn[j];
        }
        __syncthreads();
    }

    if (MODE == 1) {
#pragma unroll
        for (int i = 0; i < 8; i++) {
            int grow = row0 + ty * 8 + i;
#pragma unroll
            for (int jv = 0; jv < 2; jv++) {
                int col = n0 + tx * 8 + jv * 4;
                float4 res = *(const float4*)&Amat[grow * H_ + col];
                float4 o;
                o.x = tanhf(acc[i][jv * 4 + 0] + bias[col + 0]) + res.x;
                o.y = tanhf(acc[i][jv * 4 + 1] + bias[col + 1]) + res.y;
                o.z = tanhf(acc[i][jv * 4 + 2] + bias[col + 2]) + res.z;
                o.w = tanhf(acc[i][jv * 4 + 3] + bias[col + 3]) + res.w;
                *(float4*)&g_moe[grow * H_ + col] = o;
            }
        }
    } else {
        float part[8];
#pragma unroll
        for (int i = 0; i < 8; i++) {
            float p = 0.0f;
#pragma unroll
            for (int j = 0; j < 8; j++) {
                int col = n0 + tx * 8 + j;
                float h = acc[i][j] + bias[col];
                h = (h > 0.0f) ? h : 0.01f * h;
                p += h * w2[col];
            }
            part[i] = p;
        }
        float* red = &As[0][0];  // reuse 2048-float region (safe: synced)
#pragma unroll
        for (int i = 0; i < 8; i++) red[tx * 128 + ty * 8 + i] = part[i];
        __syncthreads();
        if (tid < 128) {
            float s = 0.0f;
#pragma unroll
            for (int t = 0; t < 16; t++) s += red[t * 128 + tid];
            atomicAdd(&g_w[row0 + tid], s);
        }
    }
}

// ---------------- tma softmax over S per batch ----------------
__global__ void tma_softmax_kernel(const int* __restrict__ seq) {
    int b = blockIdx.x;
    int t = threadIdx.x;
    __shared__ float sd[256];
    float v = -3.4e38f;
    if (t < S_) v = (seq[b * S_ + t] == 0) ? NEGV : g_w[b * S_ + t];
    sd[t] = v;
    __syncthreads();
    for (int o = 128; o; o >>= 1) { if (t < o) sd[t] = fmaxf(sd[t], sd[t + o]); __syncthreads(); }
    float m = sd[0];
    __syncthreads();
    float e = (t < S_) ? expf(v - m) : 0.0f;
    sd[t] = e;
    __syncthreads();
    for (int o = 128; o; o >>= 1) { if (t < o) sd[t] += sd[t + o]; __syncthreads(); }
    float s = sd[0];
    if (t < S_) g_w[b * S_ + t] = e / s;
}

// ---------------- LayerNorm over H, in place on g_moe ----------------
__global__ void ln_kernel(const float* __restrict__ gam, const float* __restrict__ bet) {
    int row = blockIdx.x * 8 + (threadIdx.x >> 5);
    int lane = threadIdx.x & 31;
    float* p = &g_moe[row * H_];
    float4 x[4];
    float sum = 0.0f;
#pragma unroll
    for (int q = 0; q < 4; q++) {
        x[q] = *(float4*)&p[lane * 4 + q * 128];
        sum += x[q].x + x[q].y + x[q].z + x[q].w;
    }
    for (int o = 16; o; o >>= 1) sum += __shfl_xor_sync(0xffffffffu, sum, o);
    float mu = sum * (1.0f / H_);
    float sq = 0.0f;
#pragma unroll
    for (int q = 0; q < 4; q++) {
        float a = x[q].x - mu, bb = x[q].y - mu, c = x[q].z - mu, d = x[q].w - mu;
        sq += a * a + bb * bb + c * c + d * d;
    }
    for (int o = 16; o; o >>= 1) sq += __shfl_xor_sync(0xffffffffu, sq, o);
    float rs = rsqrtf(sq * (1.0f / H_) + 1e-12f);
#pragma unroll
    for (int q = 0; q < 4; q++) {
        int col = lane * 4 + q * 128;
        float4 o4;
        o4.x = (x[q].x - mu) * rs * gam[col + 0] + bet[col + 0];
        o4.y = (x[q].y - mu) * rs * gam[col + 1] + bet[col + 1];
        o4.z = (x[q].z - mu) * rs * gam[col + 2] + bet[col + 2];
        o4.w = (x[q].w - mu) * rs * gam[col + 3] + bet[col + 3];
        *(float4*)&p[col] = o4;
    }
}

// ---------------- gates: GEMV x32 + softmax + argmax + scatter count ------
__launch_bounds__(256)
__global__ void gates_kernel(const float* __restrict__ item, const int* __restrict__ seq,
                             float* __restrict__ out_gsm) {
    __shared__ float xs[8][512];
    int tid = threadIdx.x, w = tid >> 5, lane = tid & 31;
    int row = blockIdx.x * 8 + w;
    const float* xr = &item[row * H_];
#pragma unroll
    for (int q = 0; q < 16; q++) xs[w][lane + q * 32] = xr[lane + q * 32];
    __syncwarp();
    float acc = 0.0f;
#pragma unroll 4
    for (int k = 0; k < H_; k++) acc += xs[w][k] * g_awT[k * A_ + lane];

    float mv = acc;
    int mi = lane;
    for (int o = 16; o; o >>= 1) {
        float ov = __shfl_xor_sync(0xffffffffu, mv, o);
        int oi = __shfl_xor_sync(0xffffffffu, mi, o);
        if (ov > mv || (ov == mv && oi < mi)) { mv = ov; mi = oi; }
    }
    float e = expf(acc - mv);
    float s = e;
    for (int o = 16; o; o >>= 1) s += __shfl_xor_sync(0xffffffffu, s, o);
    out_gsm[row * A_ + lane] = e / s;
    g_bij[row * A_ + lane] = acc;
    if (lane == 0 && seq[row] != 0) atomicAdd(&g_count[(row / S_) * A_ + mi], 1);
}

__global__ void mask_kernel(float* __restrict__ out_mask) {
    int i = blockIdx.x * blockDim.x + threadIdx.x;
    if (i < B_ * A_) out_mask[i] = (g_count[i] == 0) ? 1.0f : 0.0f;
}

// ---------------- routing: cijt = softmax(masked bij) * tma --------------
__global__ void cijt_kernel(const int* __restrict__ seq) {
    int tid = threadIdx.x, w = tid >> 5, lane = tid & 31;
    int row = blockIdx.x * 8 + w;
    int b = row / S_;
    float v = (g_count[b * A_ + lane] == 0) ? NEGV : g_bij[row * A_ + lane];
    float mv = v;
    for (int o = 16; o; o >>= 1) mv = fmaxf(mv, __shfl_xor_sync(0xffffffffu, mv, o));
    float e = expf(v - mv);
    float s = e;
    for (int o = 16; o; o >>= 1) s += __shfl_xor_sync(0xffffffffu, s, o);
    float c = e / s;
    if (seq[row] == 0) c = 0.0f;
    g_cijt[row * A_ + lane] = c * g_w[row];
}

// ---------------- cap[b] = cijt[b]^T (A x S) @ moe[b] (S x H) ------------
__launch_bounds__(256)
__global__ void cap_kernel(float* __restrict__ cap) {
    __shared__ float ct[8][32];
    __shared__ float ms[8][128];
    int b = blockIdx.y, nt = blockIdx.x;
    int tid = threadIdx.x, tx = tid & 31, ty = tid >> 5;
    float4 acc[4];
#pragma unroll
    for (int r = 0; r < 4; r++) acc[r] = make_float4(0.f, 0.f, 0.f, 0.f);
    const float* cij = &g_cijt[b * S_ * A_];
    const float* moe = &g_moe[b * S_ * H_ + nt * 128];
    for (int s0 = 0; s0 < S_; s0 += 8) {
        ct[ty][tx] = cij[(s0 + ty) * A_ + tx];
        *(float4*)&ms[ty][tx * 4] = *(const float4*)&moe[(s0 + ty) * H_ + tx * 4];
        __syncthreads();
#pragma unroll
        for (int ss = 0; ss < 8; ss++) {
            float4 bf = *(float4*)&ms[ss][tx * 4];
#pragma unroll
            for (int r = 0; r < 4; r++) {
                float av = ct[ss][ty + r * 8];
                acc[r].x += av * bf.x; acc[r].y += av * bf.y;
                acc[r].z += av * bf.z; acc[r].w += av * bf.w;
            }
        }
        __syncthreads();
    }
#pragma unroll
    for (int r = 0; r < 4; r++) {
        int a = ty + r * 8;
        *(float4*)&cap[(b * A_ + a) * H_ + nt * 128 + tx * 4] = acc[r];
    }
}

// ---------------- squash per (b,a) row of H ----------------
__global__ void squash_kernel(float* __restrict__ cap) {
    int row = blockIdx.x * 8 + (threadIdx.x >> 5);
    int lane = threadIdx.x & 31;
    float* p = &cap[row * H_];
    float4 x[4];
    float sq = 0.0f;
#pragma unroll
    for (int q = 0; q < 4; q++) {
        x[q] = *(float4*)&p[lane * 4 + q * 128];
        sq += x[q].x * x[q].x + x[q].y * x[q].y + x[q].z * x[q].z + x[q].w * x[q].w;
    }
    for (int o = 16; o; o >>= 1) sq += __shfl_xor_sync(0xffffffffu, sq, o);
    float sc = sq / ((1.0f + sq) * sqrtf(sq + 1e-9f));
#pragma unroll
    for (int q = 0; q < 4; q++) {
        int col = lane * 4 + q * 128;
        float4 o4 = make_float4(x[q].x * sc, x[q].y * sc, x[q].z * sc, x[q].w * sc);
        *(float4*)&p[col] = o4;
    }
}

// ---------------- bij += moe[b] (S x H) @ cap[b]^T (H x A) ---------------
__launch_bounds__(256)
__global__ void bijupd_kernel(const float* __restrict__ cap) {
    __shared__ float ms[16][65];
    __shared__ float cs[16][33];
    int b = blockIdx.y, st = blockIdx.x;
    int tid = threadIdx.x;
    int a = tid & 31, g = tid >> 5;
    float acc[8];
#pragma unroll
    for (int i = 0; i < 8; i++) acc[i] = 0.0f;
    const float* moe = &g_moe[b * S_ * H_];
    const float* cp = &cap[b * A_ * H_];
    for (int k0 = 0; k0 < H_; k0 += 16) {
        {
            int r = tid >> 2, q = tid & 3;
            int s = st * 64 + r;
            if (s > S_ - 1) s = S_ - 1;  // clamp: rows >=200 computed but never stored
            float4 v = *(const float4*)&moe[s * H_ + k0 + q * 4];
            ms[q * 4 + 0][r] = v.x; ms[q * 4 + 1][r] = v.y;
            ms[q * 4 + 2][r] = v.z; ms[q * 4 + 3][r] = v.w;
        }
#pragma unroll
        for (int i = 0; i < 2; i++) {
            int idx = tid * 2 + i;
            int aa = idx >> 4, kk = idx & 15;
            cs[kk][aa] = cp[aa * H_ + k0 + kk];
        }
        __syncthreads();
#pragma unroll
        for (int kk = 0; kk < 16; kk++) {
            float cv = cs[kk][a];
#pragma unroll
            for (int i = 0; i < 8; i++) acc[i] += ms[kk][g + i * 8] * cv;
        }
        __syncthreads();
    }
#pragma unroll
    for (int i = 0; i < 8; i++) {
        int s = st * 64 + g + i * 8;
        if (s < S_) g_bij[(b * S_ + s) * A_ + a] += acc[i];
    }
}

// ---------------- host ----------------
extern "C" void kernel_launch(void* const* d_in, const int* in_sizes, int n_in,
                              void* d_out, int out_size) {
    const float* item = (const float*)d_in[0];
    const int*   seq  = (const int*)d_in[1];
    const float* pos  = (const float*)d_in[2];
    const float* w1   = (const float*)d_in[3];
    const float* b1   = (const float*)d_in[4];
    const float* w2   = (const float*)d_in[5];
    // d_in[6] = attn_b2: softmax-invariant constant shift, mathematically a no-op
    const float* lw   = (const float*)d_in[7];
    const float* lb   = (const float*)d_in[8];
    const float* aw   = (const float*)d_in[9];
    const float* lng  = (const float*)d_in[10];
    const float* lnb  = (const float*)d_in[11];

    const size_t CAPN = (size_t)B_ * A_ * H_;   // 8388608
    const size_t GSN  = (size_t)M_ * A_;        // 3276800
    const size_t MKN  = (size_t)B_ * A_;        // 16384

    float* out_cap = (float*)d_out;
    float* out_gsm;
    float* out_mask;
    if ((size_t)out_size >= CAPN + GSN + MKN) {
        out_gsm  = out_cap + CAPN;
        out_mask = out_cap + CAPN + GSN;
    } else {  // defensive: harness may expose fewer outputs
        void* p;
        cudaGetSymbolAddress(&p, g_dummy_gates); out_gsm = (float*)p;
        cudaGetSymbolAddress(&p, g_dummy_mask);  out_mask = (float*)p;
    }

    zero_kernel<<<(M_ + 255) / 256, 256>>>();
    transpose_aw_kernel<<<(A_ * H_ + 255) / 256, 256>>>(aw);

    sgemm_kernel<0><<<dim3(4, 800), 256>>>(item, w1, pos, b1, w2);
    tma_softmax_kernel<<<B_, 256>>>(seq);

    sgemm_kernel<1><<<dim3(4, 800), 256>>>(item, lw, nullptr, lb, nullptr);
    ln_kernel<<<M_ / 8, 256>>>(lng, lnb);

    gates_kernel<<<M_ / 8, 256>>>(item, seq, out_gsm);
    mask_kernel<<<(B_ * A_ + 255) / 256, 256>>>(out_mask);

    for (int t = 0; t < 3; t++) {
        cijt_kernel<<<M_ / 8, 256>>>(seq);
        cap_kernel<<<dim3(4, B_), 256>>>(out_cap);
        squash_kernel<<<B_ * A_ / 8, 256>>>(out_cap);
        if (t < 2) bijupd_kernel<<<dim3(4, B_), 256>>>(out_cap);  // last layer's bij unused
    }
}

// round 4
// speedup vs baseline: 1.4783x; 1.4783x over previous
#include <cuda_runtime.h>
#include <cstdint>
#include <math.h>

#define B_ 512
#define S_ 200
#define H_ 512
#define A_ 32
#define M_ (B_*S_)          // 102400 rows
#define NEGV (-1e9f)

// ---------------- device scratch (no allocations allowed) ----------------
__device__ float g_moe[(M_ + 64) * H_];   // ~210MB
__device__ float g_w[M_];                 // attention logits -> tma softmax
__device__ float g_bij[M_ * A_];
__device__ float g_cijt[M_ * A_];
__device__ float g_awT[H_ * A_];
__device__ float g_wT[H_ * H_];           // transposed weight (tf32-rounded), N-major [n][k]
__device__ int   g_count[B_ * A_];
__device__ float g_dummy_gates[M_ * A_];
__device__ float g_dummy_mask[B_ * A_];

// cvt.rna.tf32.f32 needs a .b32 destination register (not .f32)
__device__ __forceinline__ float to_tf32(float x) {
    uint32_t y;
    asm("cvt.rna.tf32.f32 %0, %1;" : "=r"(y) : "f"(x));
    return __uint_as_float(y);
}

// mma.sync m16n8k8 tf32 (PTX ISA 7.0 -- compiles for compute_100)
__device__ __forceinline__ void mma_tf32(float c[4],
                                         uint32_t a0, uint32_t a1, uint32_t a2, uint32_t a3,
                                         uint32_t b0, uint32_t b1) {
    asm volatile(
        "mma.sync.aligned.m16n8k8.row.col.f32.tf32.tf32.f32 "
        "{%0,%1,%2,%3}, {%4,%5,%6,%7}, {%8,%9}, {%0,%1,%2,%3};"
        : "+f"(c[0]), "+f"(c[1]), "+f"(c[2]), "+f"(c[3])
        : "r"(a0), "r"(a1), "r"(a2), "r"(a3), "r"(b0), "r"(b1));
}

// ---------------- init ----------------
__global__ void zero_kernel() {
    int i = blockIdx.x * blockDim.x + threadIdx.x;
    if (i < M_) g_w[i] = 0.0f;
    if (i < B_ * A_) g_count[i] = 0;
}
__global__ void transpose_aw_kernel(const float* __restrict__ aw) {
    int i = blockIdx.x * blockDim.x + threadIdx.x;
    if (i < A_ * H_) {
        int a = i >> 9, k = i & 511;
        g_awT[k * A_ + a] = aw[i];
    }
}
// transpose + tf32-round the 512x512 weight: g_wT[n][k] = tf32(W[k][n])
__global__ void transpose_w_kernel(const float* __restrict__ W) {
    __shared__ float ts[32][33];
    int bx = blockIdx.x & 15, by = blockIdx.x >> 4;
    int tx = threadIdx.x & 31, ty = threadIdx.x >> 5;  // 256 thr: 32x8
#pragma unroll
    for (int r = 0; r < 4; r++)
        ts[ty + r * 8][tx] = W[(by * 32 + ty + r * 8) * H_ + bx * 32 + tx];
    __syncthreads();
#pragma unroll
    for (int r = 0; r < 4; r++)
        g_wT[(bx * 32 + ty + r * 8) * H_ + by * 32 + tx] = to_tf32(ts[tx][ty + r * 8]);
}

// =========== TF32 tensor-core GEMM: C[128x128 tile] = A[M,512] @ W[512,512] ===
// MODE 0: attention: A-load adds pos_emb; epilogue leaky(acc+b1)*w2 row-reduce.
// MODE 1: moe: epilogue tanh(acc+lin_b)+item -> g_moe.
// SMEM tiles stored k-major with stride 137 (conflict-free STS, <=2-way frag LDS).
#define KSTRIDE 137
#define TILEF (32 * KSTRIDE)           // 4384 floats per tile buffer
#define SMEM_FLOATS (4 * TILEF + 512 + 256)
#define SMEM_BYTES  (SMEM_FLOATS * 4)

template <int MODE>
__global__ void __launch_bounds__(256, 1) mma_gemm_kernel(
    const float* __restrict__ Amat, const float* __restrict__ pos,
    const float* __restrict__ p0g, const float* __restrict__ p1g) {
    extern __shared__ float sm[];
    float* red = sm + 4 * TILEF;          // [4][128]
    float* P0  = red + 512;
    float* P1  = P0 + 128;

    const int tid = threadIdx.x;
    const int lane = tid & 31;
    const int wid = tid >> 5;
    const int g = lane >> 2, q = lane & 3;
    const int warp_m = wid & 1;           // 0..1 -> 64-row half
    const int warp_n = wid >> 1;          // 0..3 -> 32-col slice
    const int row0 = blockIdx.y * 128;
    const int n0 = blockIdx.x * 128;

    if (tid < 128) {
        P0[tid] = p0g[n0 + tid];
        if (MODE == 0) P1[tid] = p1g[n0 + tid];
    }

    float c[4][4][4];
#pragma unroll
    for (int mf = 0; mf < 4; mf++)
#pragma unroll
        for (int nf = 0; nf < 4; nf++)
#pragma unroll
            for (int i = 0; i < 4; i++) c[mf][nf][i] = 0.0f;

    float4 ar[4], br[4];

    auto gload = [&](int ch) {
        const int k0 = ch * 32;
#pragma unroll
        for (int j = 0; j < 4; j++) {
            int f = tid + j * 256;
            int r = f >> 3, qc = f & 7;
            ar[j] = *(const float4*)&Amat[(row0 + r) * H_ + k0 + qc * 4];
            if (MODE == 0) {
                float4 pz = *(const float4*)&pos[((row0 + r) % S_) * H_ + k0 + qc * 4];
                ar[j].x += pz.x; ar[j].y += pz.y; ar[j].z += pz.z; ar[j].w += pz.w;
            }
            br[j] = *(const float4*)&g_wT[(n0 + r) * H_ + k0 + qc * 4];
        }
    };
    auto sstore = [&](int buf) {
        float* Ab = sm + buf * 2 * TILEF;
        float* Bb = Ab + TILEF;
#pragma unroll
        for (int j = 0; j < 4; j++) {
            int f = tid + j * 256;
            int r = f >> 3, qc = f & 7;
            int kb = qc * 4;
            Ab[(kb + 0) * KSTRIDE + r] = to_tf32(ar[j].x);
            Ab[(kb + 1) * KSTRIDE + r] = to_tf32(ar[j].y);
            Ab[(kb + 2) * KSTRIDE + r] = to_tf32(ar[j].z);
            Ab[(kb + 3) * KSTRIDE + r] = to_tf32(ar[j].w);
            Bb[(kb + 0) * KSTRIDE + r] = br[j].x;   // g_wT pre-rounded
            Bb[(kb + 1) * KSTRIDE + r] = br[j].y;
            Bb[(kb + 2) * KSTRIDE + r] = br[j].z;
            Bb[(kb + 3) * KSTRIDE + r] = br[j].w;
        }
    };

    gload(0);
    sstore(0);
    __syncthreads();

    const int mb = warp_m * 64;
    const int nb = warp_n * 32;
#pragma unroll 1
    for (int ch = 0; ch < 16; ch++) {
        const int buf = ch & 1;
        if (ch < 15) gload(ch + 1);

        const uint32_t* Ab = (const uint32_t*)(sm + buf * 2 * TILEF);
        const uint32_t* Bb = Ab + TILEF;
#pragma unroll
        for (int ks = 0; ks < 4; ks++) {
            const int kk = ks * 8;
            uint32_t af[4][4];
#pragma unroll
            for (int mf = 0; mf < 4; mf++) {
                int m = mb + mf * 16 + g;
                af[mf][0] = Ab[(kk + q) * KSTRIDE + m];
                af[mf][1] = Ab[(kk + q) * KSTRIDE + m + 8];
                af[mf][2] = Ab[(kk + q + 4) * KSTRIDE + m];
                af[mf][3] = Ab[(kk + q + 4) * KSTRIDE + m + 8];
            }
            uint32_t bf[4][2];
#pragma unroll
            for (int nf = 0; nf < 4; nf++) {
                int n = nb + nf * 8 + g;
                bf[nf][0] = Bb[(kk + q) * KSTRIDE + n];
                bf[nf][1] = Bb[(kk + q + 4) * KSTRIDE + n];
            }
#pragma unroll
            for (int mf = 0; mf < 4; mf++)
#pragma unroll
                for (int nf = 0; nf < 4; nf++)
                    mma_tf32(c[mf][nf], af[mf][0], af[mf][1], af[mf][2], af[mf][3],
                             bf[nf][0], bf[nf][1]);
        }
        if (ch < 15) sstore(buf ^ 1);
        __syncthreads();
    }

    if (MODE == 1) {
#pragma unroll
        for (int mf = 0; mf < 4; mf++) {
            int r = row0 + mb + mf * 16 + g;
#pragma unroll
            for (int nf = 0; nf < 4; nf++) {
                int lc = nb + nf * 8 + 2 * q;
                int col = n0 + lc;
                float2 res0 = *(const float2*)&Amat[r * H_ + col];
                float2 res1 = *(const float2*)&Amat[(r + 8) * H_ + col];
                float2 o0, o1;
                o0.x = tanhf(c[mf][nf][0] + P0[lc]) + res0.x;
                o0.y = tanhf(c[mf][nf][1] + P0[lc + 1]) + res0.y;
                o1.x = tanhf(c[mf][nf][2] + P0[lc]) + res1.x;
                o1.y = tanhf(c[mf][nf][3] + P0[lc + 1]) + res1.y;
                *(float2*)&g_moe[r * H_ + col] = o0;
                *(float2*)&g_moe[(r + 8) * H_ + col] = o1;
            }
        }
    } else {
        float pr[4][2];
#pragma unroll
        for (int mf = 0; mf < 4; mf++) { pr[mf][0] = 0.0f; pr[mf][1] = 0.0f; }
#pragma unroll
        for (int mf = 0; mf < 4; mf++)
#pragma unroll
            for (int nf = 0; nf < 4; nf++) {
                int lc = nb + nf * 8 + 2 * q;
                float h;
                h = c[mf][nf][0] + P0[lc];     h = (h > 0.f) ? h : 0.01f * h; pr[mf][0] += h * P1[lc];
                h = c[mf][nf][1] + P0[lc + 1]; h = (h > 0.f) ? h : 0.01f * h; pr[mf][0] += h * P1[lc + 1];
                h = c[mf][nf][2] + P0[lc];     h = (h > 0.f) ? h : 0.01f * h; pr[mf][1] += h * P1[lc];
                h = c[mf][nf][3] + P0[lc + 1]; h = (h > 0.f) ? h : 0.01f * h; pr[mf][1] += h * P1[lc + 1];
            }
#pragma unroll
        for (int mf = 0; mf < 4; mf++)
#pragma unroll
            for (int o = 1; o < 4; o <<= 1) {
                pr[mf][0] += __shfl_xor_sync(0xffffffffu, pr[mf][0], o);
                pr[mf][1] += __shfl_xor_sync(0xffffffffu, pr[mf][1], o);
            }
        if (q == 0) {
#pragma unroll
            for (int mf = 0; mf < 4; mf++) {
                red[warp_n * 128 + mb + mf * 16 + g] = pr[mf][0];
                red[warp_n * 128 + mb + mf * 16 + g + 8] = pr[mf][1];
            }
        }
        __syncthreads();
        if (tid < 128) {
            float s = red[tid] + red[128 + tid] + red[256 + tid] + red[384 + tid];
            atomicAdd(&g_w[row0 + tid], s);
        }
    }
}

// ---------------- tma softmax over S per batch ----------------
__global__ void tma_softmax_kernel(const int* __restrict__ seq) {
    int b = blockIdx.x;
    int t = threadIdx.x;
    __shared__ float sd[256];
    float v = -3.4e38f;
    if (t < S_) v = (seq[b * S_ + t] == 0) ? NEGV : g_w[b * S_ + t];
    sd[t] = v;
    __syncthreads();
    for (int o = 128; o; o >>= 1) { if (t < o) sd[t] = fmaxf(sd[t], sd[t + o]); __syncthreads(); }
    float m = sd[0];
    __syncthreads();
    float e = (t < S_) ? expf(v - m) : 0.0f;
    sd[t] = e;
    __syncthreads();
    for (int o = 128; o; o >>= 1) { if (t < o) sd[t] += sd[t + o]; __syncthreads(); }
    float s = sd[0];
    if (t < S_) g_w[b * S_ + t] = e / s;
}

// ---------------- LayerNorm over H, in place on g_moe ----------------
__global__ void ln_kernel(const float* __restrict__ gam, const float* __restrict__ bet) {
    int row = blockIdx.x * 8 + (threadIdx.x >> 5);
    int lane = threadIdx.x & 31;
    float* p = &g_moe[row * H_];
    float4 x[4];
    float sum = 0.0f;
#pragma unroll
    for (int q = 0; q < 4; q++) {
        x[q] = *(float4*)&p[lane * 4 + q * 128];
        sum += x[q].x + x[q].y + x[q].z + x[q].w;
    }
    for (int o = 16; o; o >>= 1) sum += __shfl_xor_sync(0xffffffffu, sum, o);
    float mu = sum * (1.0f / H_);
    float sq = 0.0f;
#pragma unroll
    for (int q = 0; q < 4; q++) {
        float a = x[q].x - mu, bb = x[q].y - mu, c = x[q].z - mu, d = x[q].w - mu;
        sq += a * a + bb * bb + c * c + d * d;
    }
    for (int o = 16; o; o >>= 1) sq += __shfl_xor_sync(0xffffffffu, sq, o);
    float rs = rsqrtf(sq * (1.0f / H_) + 1e-12f);
#pragma unroll
    for (int q = 0; q < 4; q++) {
        int col = lane * 4 + q * 128;
        float4 o4;
        o4.x = (x[q].x - mu) * rs * gam[col + 0] + bet[col + 0];
        o4.y = (x[q].y - mu) * rs * gam[col + 1] + bet[col + 1];
        o4.z = (x[q].z - mu) * rs * gam[col + 2] + bet[col + 2];
        o4.w = (x[q].w - mu) * rs * gam[col + 3] + bet[col + 3];
        *(float4*)&p[col] = o4;
    }
}

// ---------------- gates: GEMV x32 + softmax + argmax + scatter count ------
__launch_bounds__(256)
__global__ void gates_kernel(const float* __restrict__ item, const int* __restrict__ seq,
                             float* __restrict__ out_gsm) {
    __shared__ float xs[8][512];
    int tid = threadIdx.x, w = tid >> 5, lane = tid & 31;
    int row = blockIdx.x * 8 + w;
    const float* xr = &item[row * H_];
#pragma unroll
    for (int q = 0; q < 16; q++) xs[w][lane + q * 32] = xr[lane + q * 32];
    __syncwarp();
    float acc = 0.0f;
#pragma unroll 4
    for (int k = 0; k < H_; k++) acc += xs[w][k] * g_awT[k * A_ + lane];

    float mv = acc;
    int mi = lane;
    for (int o = 16; o; o >>= 1) {
        float ov = __shfl_xor_sync(0xffffffffu, mv, o);
        int oi = __shfl_xor_sync(0xffffffffu, mi, o);
        if (ov > mv || (ov == mv && oi < mi)) { mv = ov; mi = oi; }
    }
    float e = expf(acc - mv);
    float s = e;
    for (int o = 16; o; o >>= 1) s += __shfl_xor_sync(0xffffffffu, s, o);
    out_gsm[row * A_ + lane] = e / s;
    g_bij[row * A_ + lane] = acc;
    if (lane == 0 && seq[row] != 0) atomicAdd(&g_count[(row / S_) * A_ + mi], 1);
}

__global__ void mask_kernel(float* __restrict__ out_mask) {
    int i = blockIdx.x * blockDim.x + threadIdx.x;
    if (i < B_ * A_) out_mask[i] = (g_count[i] == 0) ? 1.0f : 0.0f;
}

// ---------------- routing: cijt = softmax(masked bij) * tma --------------
__global__ void cijt_kernel(const int* __restrict__ seq) {
    int tid = threadIdx.x, w = tid >> 5, lane = tid & 31;
    int row = blockIdx.x * 8 + w;
    int b = row / S_;
    float v = (g_count[b * A_ + lane] == 0) ? NEGV : g_bij[row * A_ + lane];
    float mv = v;
    for (int o = 16; o; o >>= 1) mv = fmaxf(mv, __shfl_xor_sync(0xffffffffu, mv, o));
    float e = expf(v - mv);
    float s = e;
    for (int o = 16; o; o >>= 1) s += __shfl_xor_sync(0xffffffffu, s, o);
    float c = e / s;
    if (seq[row] == 0) c = 0.0f;
    g_cijt[row * A_ + lane] = c * g_w[row];
}

// ---------------- cap[b] = cijt[b]^T (A x S) @ moe[b] (S x H) ------------
__launch_bounds__(256)
__global__ void cap_kernel(float* __restrict__ cap) {
    __shared__ float ct[8][32];
    __shared__ float ms[8][128];
    int b = blockIdx.y, nt = blockIdx.x;
    int tid = threadIdx.x, tx = tid & 31, ty = tid >> 5;
    float4 acc[4];
#pragma unroll
    for (int r = 0; r < 4; r++) acc[r] = make_float4(0.f, 0.f, 0.f, 0.f);
    const float* cij = &g_cijt[b * S_ * A_];
    const float* moe = &g_moe[b * S_ * H_ + nt * 128];
    for (int s0 = 0; s0 < S_; s0 += 8) {
        ct[ty][tx] = cij[(s0 + ty) * A_ + tx];
        *(float4*)&ms[ty][tx * 4] = *(const float4*)&moe[(s0 + ty) * H_ + tx * 4];
        __syncthreads();
#pragma unroll
        for (int ss = 0; ss < 8; ss++) {
            float4 bf = *(float4*)&ms[ss][tx * 4];
#pragma unroll
            for (int r = 0; r < 4; r++) {
                float av = ct[ss][ty + r * 8];
                acc[r].x += av * bf.x; acc[r].y += av * bf.y;
                acc[r].z += av * bf.z; acc[r].w += av * bf.w;
            }
        }
        __syncthreads();
    }
#pragma unroll
    for (int r = 0; r < 4; r++) {
        int a = ty + r * 8;
        *(float4*)&cap[(b * A_ + a) * H_ + nt * 128 + tx * 4] = acc[r];
    }
}

// ---------------- squash per (b,a) row of H ----------------
__global__ void squash_kernel(float* __restrict__ cap) {
    int row = blockIdx.x * 8 + (threadIdx.x >> 5);
    int lane = threadIdx.x & 31;
    float* p = &cap[row * H_];
    float4 x[4];
    float sq = 0.0f;
#pragma unroll
    for (int q = 0; q < 4; q++) {
        x[q] = *(float4*)&p[lane * 4 + q * 128];
        sq += x[q].x * x[q].x + x[q].y * x[q].y + x[q].z * x[q].z + x[q].w * x[q].w;
    }
    for (int o = 16; o; o >>= 1) sq += __shfl_xor_sync(0xffffffffu, sq, o);
    float sc = sq / ((1.0f + sq) * sqrtf(sq + 1e-9f));
#pragma unroll
    for (int q = 0; q < 4; q++) {
        int col = lane * 4 + q * 128;
        float4 o4 = make_float4(x[q].x * sc, x[q].y * sc, x[q].z * sc, x[q].w * sc);
        *(float4*)&p[col] = o4;
    }
}

// ---------------- bij += moe[b] (S x H) @ cap[b]^T (H x A) ---------------
__launch_bounds__(256)
__global__ void bijupd_kernel(const float* __restrict__ cap) {
    __shared__ float ms[16][65];
    __shared__ float cs[16][33];
    int b = blockIdx.y, st = blockIdx.x;
    int tid = threadIdx.x;
    int a = tid & 31, g = tid >> 5;
    float acc[8];
#pragma unroll
    for (int i = 0; i < 8; i++) acc[i] = 0.0f;
    const float* moe = &g_moe[b * S_ * H_];
    const float* cp = &cap[b * A_ * H_];
    for (int k0 = 0; k0 < H_; k0 += 16) {
        {
            int r = tid >> 2, q = tid & 3;
            int s = st * 64 + r;
            if (s > S_ - 1) s = S_ - 1;
            float4 v = *(const float4*)&moe[s * H_ + k0 + q * 4];
            ms[q * 4 + 0][r] = v.x; ms[q * 4 + 1][r] = v.y;
            ms[q * 4 + 2][r] = v.z; ms[q * 4 + 3][r] = v.w;
        }
#pragma unroll
        for (int i = 0; i < 2; i++) {
            int idx = tid * 2 + i;
            int aa = idx >> 4, kk = idx & 15;
            cs[kk][aa] = cp[aa * H_ + k0 + kk];
        }
        __syncthreads();
#pragma unroll
        for (int kk = 0; kk < 16; kk++) {
            float cv = cs[kk][a];
#pragma unroll
            for (int i = 0; i < 8; i++) acc[i] += ms[kk][g + i * 8] * cv;
        }
        __syncthreads();
    }
#pragma unroll
    for (int i = 0; i < 8; i++) {
        int s = st * 64 + g + i * 8;
        if (s < S_) g_bij[(b * S_ + s) * A_ + a] += acc[i];
    }
}

// ---------------- host ----------------
extern "C" void kernel_launch(void* const* d_in, const int* in_sizes, int n_in,
                              void* d_out, int out_size) {
    const float* item = (const float*)d_in[0];
    const int*   seq  = (const int*)d_in[1];
    const float* pos  = (const float*)d_in[2];
    const float* w1   = (const float*)d_in[3];
    const float* b1   = (const float*)d_in[4];
    const float* w2   = (const float*)d_in[5];
    // d_in[6] = attn_b2: softmax-invariant constant shift, a no-op
    const float* lw   = (const float*)d_in[7];
    const float* lb   = (const float*)d_in[8];
    const float* aw   = (const float*)d_in[9];
    const float* lng  = (const float*)d_in[10];
    const float* lnb  = (const float*)d_in[11];

    const size_t CAPN = (size_t)B_ * A_ * H_;
    const size_t GSN  = (size_t)M_ * A_;
    const size_t MKN  = (size_t)B_ * A_;

    float* out_cap = (float*)d_out;
    float* out_gsm;
    float* out_mask;
    if ((size_t)out_size >= CAPN + GSN + MKN) {
        out_gsm  = out_cap + CAPN;
        out_mask = out_cap + CAPN + GSN;
    } else {
        void* p;
        cudaGetSymbolAddress(&p, g_dummy_gates); out_gsm = (float*)p;
        cudaGetSymbolAddress(&p, g_dummy_mask);  out_mask = (float*)p;
    }

    cudaFuncSetAttribute(mma_gemm_kernel<0>, cudaFuncAttributeMaxDynamicSharedMemorySize,
                         SMEM_BYTES);
    cudaFuncSetAttribute(mma_gemm_kernel<1>, cudaFuncAttributeMaxDynamicSharedMemorySize,
                         SMEM_BYTES);

    zero_kernel<<<(M_ + 255) / 256, 256>>>();
    transpose_aw_kernel<<<(A_ * H_ + 255) / 256, 256>>>(aw);

    transpose_w_kernel<<<256, 256>>>(w1);
    mma_gemm_kernel<0><<<dim3(4, 800), 256, SMEM_BYTES>>>(item, pos, b1, w2);
    tma_softmax_kernel<<<B_, 256>>>(seq);

    transpose_w_kernel<<<256, 256>>>(lw);
    mma_gemm_kernel<1><<<dim3(4, 800), 256, SMEM_BYTES>>>(item, nullptr, lb, nullptr);
    ln_kernel<<<M_ / 8, 256>>>(lng, lnb);

    gates_kernel<<<M_ / 8, 256>>>(item, seq, out_gsm);
    mask_kernel<<<(B_ * A_ + 255) / 256, 256>>>(out_mask);

    for (int t = 0; t < 3; t++) {
        cijt_kernel<<<M_ / 8, 256>>>(seq);
        cap_kernel<<<dim3(4, B_), 256>>>(out_cap);
        squash_kernel<<<B_ * A_ / 8, 256>>>(out_cap);
        if (t < 2) bijupd_kernel<<<dim3(4, B_), 256>>>(out_cap);
    }
}

// round 5
// speedup vs baseline: 1.7565x; 1.1882x over previous
#include <cuda_runtime.h>
#include <cuda_bf16.h>
#include <cstdint>
#include <math.h>

#define B_ 512
#define S_ 200
#define H_ 512
#define A_ 32
#define M_ (B_*S_)          // 102400 rows
#define NEGV (-1e9f)

// ---------------- device scratch (no allocations allowed) ----------------
__device__ float g_moe[(M_ + 64) * H_];   // ~210MB
__device__ float g_w[M_];                 // attention logits -> tma softmax
__device__ float g_bij[M_ * A_];
__device__ float g_cijt[M_ * A_];
__device__ float g_awT[H_ * A_];
__device__ __nv_bfloat16 g_wTh[H_ * H_];  // transposed weight, bf16, N-major [n][k]
__device__ int   g_count[B_ * A_];
__device__ float g_dummy_gates[M_ * A_];
__device__ float g_dummy_mask[B_ * A_];

// ---------------- PTX helpers (family-portable) ----------------
__device__ __forceinline__ uint32_t pk_bf16x2(float x, float y) {
    __nv_bfloat162 t = __float22bfloat162_rn(make_float2(x, y));
    return *(uint32_t*)&t;
}
__device__ __forceinline__ uint32_t smem_u32(const void* p) {
    uint32_t a;
    asm("{ .reg .u64 t; cvta.to.shared.u64 t, %1; cvt.u32.u64 %0, t; }" : "=r"(a) : "l"(p));
    return a;
}
__device__ __forceinline__ void ldm4(uint32_t r[4], uint32_t addr) {
    asm volatile("ldmatrix.sync.aligned.m8n8.x4.shared.b16 {%0,%1,%2,%3}, [%4];"
                 : "=r"(r[0]), "=r"(r[1]), "=r"(r[2]), "=r"(r[3]) : "r"(addr));
}
__device__ __forceinline__ void mma_bf16(float c[4], const uint32_t a[4],
                                         uint32_t b0, uint32_t b1) {
    asm volatile(
        "mma.sync.aligned.m16n8k16.row.col.f32.bf16.bf16.f32 "
        "{%0,%1,%2,%3},{%4,%5,%6,%7},{%8,%9},{%0,%1,%2,%3};"
        : "+f"(c[0]), "+f"(c[1]), "+f"(c[2]), "+f"(c[3])
        : "r"(a[0]), "r"(a[1]), "r"(a[2]), "r"(a[3]), "r"(b0), "r"(b1));
}
#define SWZ(off) ((off) ^ (((off) >> 3) & 0x70))

// ---------------- init ----------------
__global__ void zero_kernel() {
    int i = blockIdx.x * blockDim.x + threadIdx.x;
    if (i < M_) g_w[i] = 0.0f;
    if (i < B_ * A_) g_count[i] = 0;
}
__global__ void transpose_aw_kernel(const float* __restrict__ aw) {
    int i = blockIdx.x * blockDim.x + threadIdx.x;
    if (i < A_ * H_) {
        int a = i >> 9, k = i & 511;
        g_awT[k * A_ + a] = aw[i];
    }
}
// transpose + bf16-round the 512x512 weight: g_wTh[n][k] = bf16(W[k][n])
__global__ void transpose_w_kernel(const float* __restrict__ W) {
    __shared__ float ts[32][33];
    int bx = blockIdx.x & 15, by = blockIdx.x >> 4;
    int tx = threadIdx.x & 31, ty = threadIdx.x >> 5;  // 256 thr: 32x8
#pragma unroll
    for (int r = 0; r < 4; r++)
        ts[ty + r * 8][tx] = W[(by * 32 + ty + r * 8) * H_ + bx * 32 + tx];
    __syncthreads();
#pragma unroll
    for (int r = 0; r < 4; r++)
        g_wTh[(bx * 32 + ty + r * 8) * H_ + by * 32 + tx] =
            __float2bfloat16_rn(ts[tx][ty + r * 8]);
}

// ====== bf16 ldmatrix tensor-core GEMM: C[128x128] = A[M,512] @ W[512,512] ====
// MODE 0: attention: A-load adds pos_emb; epilogue leaky(acc+b1)*w2 row-reduce.
// MODE 1: moe: epilogue tanh(acc+lin_b)+item -> g_moe.
// Staging: K=64 chunks; A/B tiles 128 rows x 64 bf16 (128B rows), SW128 swizzle.
#define BUF_BYTES 32768                 // A(16KB) + B(16KB) per buffer
#define RED_OFF   (2 * BUF_BYTES)       // byte 65536: red[512] floats
#define SMEM_BYTES (RED_OFF + 512*4 + 128*4 + 128*4 + 128)

template <int MODE>
__global__ void __launch_bounds__(256, 1) mma_gemm_kernel(
    const float* __restrict__ Amat, const float* __restrict__ pos,
    const float* __restrict__ p0g, const float* __restrict__ p1g) {
    extern __shared__ float sm[];
    float* red = (float*)((char*)sm + RED_OFF);   // [4][128]
    float* P0  = red + 512;
    float* P1  = P0 + 128;

    const int tid = threadIdx.x;
    const int lane = tid & 31;
    const int wid = tid >> 5;
    const int g = lane >> 2, q = lane & 3;
    const int warp_m = wid & 1;           // 0..1 -> 64-row half
    const int warp_n = wid >> 1;          // 0..3 -> 32-col slice
    const int row0 = blockIdx.y * 128;
    const int n0 = blockIdx.x * 128;
    const uint32_t sbase = smem_u32(sm);

    // ldmatrix lane->row/unit decomposition
    const int lmA = lane & 15;            // A: row offset within 16
    const int uhA = lane >> 4;            // A: unit half (k 0-7 vs 8-15)
    const int lmB = (lane & 7) + ((lane >> 4) << 3);  // B: row offset within 16
    const int uhB = (lane >> 3) & 1;      // B: unit half

    if (tid < 128) {
        P0[tid] = p0g[n0 + tid];
        if (MODE == 0) P1[tid] = p1g[n0 + tid];
    }

    float c[4][4][4];
#pragma unroll
    for (int mf = 0; mf < 4; mf++)
#pragma unroll
        for (int nf = 0; nf < 4; nf++)
#pragma unroll
            for (int i = 0; i < 4; i++) c[mf][nf][i] = 0.0f;

    float4 fa[2][4];     // A staging: 2 (row,qc) pairs x 16 floats
    uint4  bb[2][2];     // B staging: 2 pairs x 32 bytes bf16

    auto gload = [&](int ch) {
        const int k0 = ch * 64;
#pragma unroll
        for (int j = 0; j < 2; j++) {
            int idx = tid + j * 256;            // 0..511
            int r = idx >> 2, qc = idx & 3;     // row 0..127, 16-float segment
            const float* ap = &Amat[(row0 + r) * H_ + k0 + qc * 16];
#pragma unroll
            for (int v = 0; v < 4; v++) fa[j][v] = *(const float4*)(ap + v * 4);
            if (MODE == 0) {
                const float* pp = &pos[((row0 + r) % S_) * H_ + k0 + qc * 16];
#pragma unroll
                for (int v = 0; v < 4; v++) {
                    float4 pz = *(const float4*)(pp + v * 4);
                    fa[j][v].x += pz.x; fa[j][v].y += pz.y;
                    fa[j][v].z += pz.z; fa[j][v].w += pz.w;
                }
            }
            const __nv_bfloat16* bp = &g_wTh[(n0 + r) * H_ + k0 + qc * 16];
            bb[j][0] = *(const uint4*)bp;
            bb[j][1] = *(const uint4*)(bp + 8);
        }
    };
    auto sstore = [&](int buf) {
        char* Ab = (char*)sm + buf * BUF_BYTES;
        char* Bb = Ab + 16384;
#pragma unroll
        for (int j = 0; j < 2; j++) {
            int idx = tid + j * 256;
            int r = idx >> 2, qc = idx & 3;
            int base = r * 128 + qc * 32;
            uint4 pa0, pa1;
            pa0.x = pk_bf16x2(fa[j][0].x, fa[j][0].y);
            pa0.y = pk_bf16x2(fa[j][0].z, fa[j][0].w);
            pa0.z = pk_bf16x2(fa[j][1].x, fa[j][1].y);
            pa0.w = pk_bf16x2(fa[j][1].z, fa[j][1].w);
            pa1.x = pk_bf16x2(fa[j][2].x, fa[j][2].y);
            pa1.y = pk_bf16x2(fa[j][2].z, fa[j][2].w);
            pa1.z = pk_bf16x2(fa[j][3].x, fa[j][3].y);
            pa1.w = pk_bf16x2(fa[j][3].z, fa[j][3].w);
            *(uint4*)(Ab + SWZ(base)) = pa0;
            *(uint4*)(Ab + SWZ(base + 16)) = pa1;
            *(uint4*)(Bb + SWZ(base)) = bb[j][0];
            *(uint4*)(Bb + SWZ(base + 16)) = bb[j][1];
        }
    };

    gload(0);
    sstore(0);
    __syncthreads();

    const int mb = warp_m * 64;
    const int nb = warp_n * 32;
#pragma unroll 1
    for (int ch = 0; ch < 8; ch++) {
        const int buf = ch & 1;
        if (ch < 7) gload(ch + 1);

        const uint32_t Au = sbase + buf * BUF_BYTES;
        const uint32_t Bu = Au + 16384;
#pragma unroll
        for (int ks = 0; ks < 4; ks++) {
            uint32_t af[4][4];
#pragma unroll
            for (int mf = 0; mf < 4; mf++) {
                int off = (mb + mf * 16 + lmA) * 128 + (2 * ks + uhA) * 16;
                ldm4(af[mf], Au + SWZ(off));
            }
            uint32_t bfr[2][4];
#pragma unroll
            for (int nh = 0; nh < 2; nh++) {
                int off = (nb + nh * 16 + lmB) * 128 + (2 * ks + uhB) * 16;
                ldm4(bfr[nh], Bu + SWZ(off));
            }
#pragma unroll
            for (int mf = 0; mf < 4; mf++)
#pragma unroll
                for (int nf = 0; nf < 4; nf++)
                    mma_bf16(c[mf][nf], af[mf], bfr[nf >> 1][(nf & 1) * 2],
                             bfr[nf >> 1][(nf & 1) * 2 + 1]);
        }
        if (ch < 7) sstore(buf ^ 1);
        __syncthreads();
    }

    if (MODE == 1) {
#pragma unroll
        for (int mf = 0; mf < 4; mf++) {
            int r = row0 + mb + mf * 16 + g;
#pragma unroll
            for (int nf = 0; nf < 4; nf++) {
                int lc = nb + nf * 8 + 2 * q;
                int col = n0 + lc;
                float2 res0 = *(const float2*)&Amat[r * H_ + col];
                float2 res1 = *(const float2*)&Amat[(r + 8) * H_ + col];
                float2 o0, o1;
                o0.x = tanhf(c[mf][nf][0] + P0[lc]) + res0.x;
                o0.y = tanhf(c[mf][nf][1] + P0[lc + 1]) + res0.y;
                o1.x = tanhf(c[mf][nf][2] + P0[lc]) + res1.x;
                o1.y = tanhf(c[mf][nf][3] + P0[lc + 1]) + res1.y;
                *(float2*)&g_moe[r * H_ + col] = o0;
                *(float2*)&g_moe[(r + 8) * H_ + col] = o1;
            }
        }
    } else {
        float pr[4][2];
#pragma unroll
        for (int mf = 0; mf < 4; mf++) { pr[mf][0] = 0.0f; pr[mf][1] = 0.0f; }
#pragma unroll
        for (int mf = 0; mf < 4; mf++)
#pragma unroll
            for (int nf = 0; nf < 4; nf++) {
                int lc = nb + nf * 8 + 2 * q;
                float h;
                h = c[mf][nf][0] + P0[lc];     h = (h > 0.f) ? h : 0.01f * h; pr[mf][0] += h * P1[lc];
                h = c[mf][nf][1] + P0[lc + 1]; h = (h > 0.f) ? h : 0.01f * h; pr[mf][0] += h * P1[lc + 1];
                h = c[mf][nf][2] + P0[lc];     h = (h > 0.f) ? h : 0.01f * h; pr[mf][1] += h * P1[lc];
                h = c[mf][nf][3] + P0[lc + 1]; h = (h > 0.f) ? h : 0.01f * h; pr[mf][1] += h * P1[lc + 1];
            }
#pragma unroll
        for (int mf = 0; mf < 4; mf++)
#pragma unroll
            for (int o = 1; o < 4; o <<= 1) {
                pr[mf][0] += __shfl_xor_sync(0xffffffffu, pr[mf][0], o);
                pr[mf][1] += __shfl_xor_sync(0xffffffffu, pr[mf][1], o);
            }
        if (q == 0) {
#pragma unroll
            for (int mf = 0; mf < 4; mf++) {
                red[warp_n * 128 + mb + mf * 16 + g] = pr[mf][0];
                red[warp_n * 128 + mb + mf * 16 + g + 8] = pr[mf][1];
            }
        }
        __syncthreads();
        if (tid < 128) {
            float s = red[tid] + red[128 + tid] + red[256 + tid] + red[384 + tid];
            atomicAdd(&g_w[row0 + tid], s);
        }
    }
}

// ---------------- tma softmax over S per batch ----------------
__global__ void tma_softmax_kernel(const int* __restrict__ seq) {
    int b = blockIdx.x;
    int t = threadIdx.x;
    __shared__ float sd[256];
    float v = -3.4e38f;
    if (t < S_) v = (seq[b * S_ + t] == 0) ? NEGV : g_w[b * S_ + t];
    sd[t] = v;
    __syncthreads();
    for (int o = 128; o; o >>= 1) { if (t < o) sd[t] = fmaxf(sd[t], sd[t + o]); __syncthreads(); }
    float m = sd[0];
    __syncthreads();
    float e = (t < S_) ? expf(v - m) : 0.0f;
    sd[t] = e;
    __syncthreads();
    for (int o = 128; o; o >>= 1) { if (t < o) sd[t] += sd[t + o]; __syncthreads(); }
    float s = sd[0];
    if (t < S_) g_w[b * S_ + t] = e / s;
}

// ---------------- LayerNorm over H, in place on g_moe ----------------
__global__ void ln_kernel(const float* __restrict__ gam, const float* __restrict__ bet) {
    int row = blockIdx.x * 8 + (threadIdx.x >> 5);
    int lane = threadIdx.x & 31;
    float* p = &g_moe[row * H_];
    float4 x[4];
    float sum = 0.0f;
#pragma unroll
    for (int q = 0; q < 4; q++) {
        x[q] = *(float4*)&p[lane * 4 + q * 128];
        sum += x[q].x + x[q].y + x[q].z + x[q].w;
    }
    for (int o = 16; o; o >>= 1) sum += __shfl_xor_sync(0xffffffffu, sum, o);
    float mu = sum * (1.0f / H_);
    float sq = 0.0f;
#pragma unroll
    for (int q = 0; q < 4; q++) {
        float a = x[q].x - mu, bb = x[q].y - mu, c = x[q].z - mu, d = x[q].w - mu;
        sq += a * a + bb * bb + c * c + d * d;
    }
    for (int o = 16; o; o >>= 1) sq += __shfl_xor_sync(0xffffffffu, sq, o);
    float rs = rsqrtf(sq * (1.0f / H_) + 1e-12f);
#pragma unroll
    for (int q = 0; q < 4; q++) {
        int col = lane * 4 + q * 128;
        float4 o4;
        o4.x = (x[q].x - mu) * rs * gam[col + 0] + bet[col + 0];
        o4.y = (x[q].y - mu) * rs * gam[col + 1] + bet[col + 1];
        o4.z = (x[q].z - mu) * rs * gam[col + 2] + bet[col + 2];
        o4.w = (x[q].w - mu) * rs * gam[col + 3] + bet[col + 3];
        *(float4*)&p[col] = o4;
    }
}

// ---------------- gates: GEMV x32 + softmax + argmax + scatter count ------
__launch_bounds__(256)
__global__ void gates_kernel(const float* __restrict__ item, const int* __restrict__ seq,
                             float* __restrict__ out_gsm) {
    __shared__ float xs[8][512];
    int tid = threadIdx.x, w = tid >> 5, lane = tid & 31;
    int row = blockIdx.x * 8 + w;
    const float* xr = &item[row * H_];
#pragma unroll
    for (int q = 0; q < 16; q++) xs[w][lane + q * 32] = xr[lane + q * 32];
    __syncwarp();
    float acc = 0.0f;
#pragma unroll 4
    for (int k = 0; k < H_; k++) acc += xs[w][k] * g_awT[k * A_ + lane];

    float mv = acc;
    int mi = lane;
    for (int o = 16; o; o >>= 1) {
        float ov = __shfl_xor_sync(0xffffffffu, mv, o);
        int oi = __shfl_xor_sync(0xffffffffu, mi, o);
        if (ov > mv || (ov == mv && oi < mi)) { mv = ov; mi = oi; }
    }
    float e = expf(acc - mv);
    float s = e;
    for (int o = 16; o; o >>= 1) s += __shfl_xor_sync(0xffffffffu, s, o);
    out_gsm[row * A_ + lane] = e / s;
    g_bij[row * A_ + lane] = acc;
    if (lane == 0 && seq[row] != 0) atomicAdd(&g_count[(row / S_) * A_ + mi], 1);
}

__global__ void mask_kernel(float* __restrict__ out_mask) {
    int i = blockIdx.x * blockDim.x + threadIdx.x;
    if (i < B_ * A_) out_mask[i] = (g_count[i] == 0) ? 1.0f : 0.0f;
}

// ---------------- routing: cijt = softmax(masked bij) * tma --------------
__global__ void cijt_kernel(const int* __restrict__ seq) {
    int tid = threadIdx.x, w = tid >> 5, lane = tid & 31;
    int row = blockIdx.x * 8 + w;
    int b = row / S_;
    float v = (g_count[b * A_ + lane] == 0) ? NEGV : g_bij[row * A_ + lane];
    float mv = v;
    for (int o = 16; o; o >>= 1) mv = fmaxf(mv, __shfl_xor_sync(0xffffffffu, mv, o));
    float e = expf(v - mv);
    float s = e;
    for (int o = 16; o; o >>= 1) s += __shfl_xor_sync(0xffffffffu, s, o);
    float c = e / s;
    if (seq[row] == 0) c = 0.0f;
    g_cijt[row * A_ + lane] = c * g_w[row];
}

// ---------------- cap[b] = cijt[b]^T (A x S) @ moe[b] (S x H) ------------
__launch_bounds__(256)
__global__ void cap_kernel(float* __restrict__ cap) {
    __shared__ float ct[8][32];
    __shared__ float ms[8][128];
    int b = blockIdx.y, nt = blockIdx.x;
    int tid = threadIdx.x, tx = tid & 31, ty = tid >> 5;
    float4 acc[4];
#pragma unroll
    for (int r = 0; r < 4; r++) acc[r] = make_float4(0.f, 0.f, 0.f, 0.f);
    const float* cij = &g_cijt[b * S_ * A_];
    const float* moe = &g_moe[b * S_ * H_ + nt * 128];
    for (int s0 = 0; s0 < S_; s0 += 8) {
        ct[ty][tx] = cij[(s0 + ty) * A_ + tx];
        *(float4*)&ms[ty][tx * 4] = *(const float4*)&moe[(s0 + ty) * H_ + tx * 4];
        __syncthreads();
#pragma unroll
        for (int ss = 0; ss < 8; ss++) {
            float4 bf = *(float4*)&ms[ss][tx * 4];
#pragma unroll
            for (int r = 0; r < 4; r++) {
                float av = ct[ss][ty + r * 8];
                acc[r].x += av * bf.x; acc[r].y += av * bf.y;
                acc[r].z += av * bf.z; acc[r].w += av * bf.w;
            }
        }
        __syncthreads();
    }
#pragma unroll
    for (int r = 0; r < 4; r++) {
        int a = ty + r * 8;
        *(float4*)&cap[(b * A_ + a) * H_ + nt * 128 + tx * 4] = acc[r];
    }
}

// ---------------- squash per (b,a) row of H ----------------
__global__ void squash_kernel(float* __restrict__ cap) {
    int row = blockIdx.x * 8 + (threadIdx.x >> 5);
    int lane = threadIdx.x & 31;
    float* p = &cap[row * H_];
    float4 x[4];
    float sq = 0.0f;
#pragma unroll
    for (int q = 0; q < 4; q++) {
        x[q] = *(float4*)&p[lane * 4 + q * 128];
        sq += x[q].x * x[q].x + x[q].y * x[q].y + x[q].z * x[q].z + x[q].w * x[q].w;
    }
    for (int o = 16; o; o >>= 1) sq += __shfl_xor_sync(0xffffffffu, sq, o);
    float sc = sq / ((1.0f + sq) * sqrtf(sq + 1e-9f));
#pragma unroll
    for (int q = 0; q < 4; q++) {
        int col = lane * 4 + q * 128;
        float4 o4 = make_float4(x[q].x * sc, x[q].y * sc, x[q].z * sc, x[q].w * sc);
        *(float4*)&p[col] = o4;
    }
}

// ---------------- bij += moe[b] (S x H) @ cap[b]^T (H x A) ---------------
__launch_bounds__(256)
__global__ void bijupd_kernel(const float* __restrict__ cap) {
    __shared__ float ms[16][65];
    __shared__ float cs[16][33];
    int b = blockIdx.y, st = blockIdx.x;
    int tid = threadIdx.x;
    int a = tid & 31, g = tid >> 5;
    float acc[8];
#pragma unroll
    for (int i = 0; i < 8; i++) acc[i] = 0.0f;
    const float* moe = &g_moe[b * S_ * H_];
    const float* cp = &cap[b * A_ * H_];
    for (int k0 = 0; k0 < H_; k0 += 16) {
        {
            int r = tid >> 2, q = tid & 3;
            int s = st * 64 + r;
            if (s > S_ - 1) s = S_ - 1;
            float4 v = *(const float4*)&moe[s * H_ + k0 + q * 4];
            ms[q * 4 + 0][r] = v.x; ms[q * 4 + 1][r] = v.y;
            ms[q * 4 + 2][r] = v.z; ms[q * 4 + 3][r] = v.w;
        }
#pragma unroll
        for (int i = 0; i < 2; i++) {
            int idx = tid * 2 + i;
            int aa = idx >> 4, kk = idx & 15;
            cs[kk][aa] = cp[aa * H_ + k0 + kk];
        }
        __syncthreads();
#pragma unroll
        for (int kk = 0; kk < 16; kk++) {
            float cv = cs[kk][a];
#pragma unroll
            for (int i = 0; i < 8; i++) acc[i] += ms[kk][g + i * 8] * cv;
        }
        __syncthreads();
    }
#pragma unroll
    for (int i = 0; i < 8; i++) {
        int s = st * 64 + g + i * 8;
        if (s < S_) g_bij[(b * S_ + s) * A_ + a] += acc[i];
    }
}

// ---------------- host ----------------
extern "C" void kernel_launch(void* const* d_in, const int* in_sizes, int n_in,
                              void* d_out, int out_size) {
    const float* item = (const float*)d_in[0];
    const int*   seq  = (const int*)d_in[1];
    const float* pos  = (const float*)d_in[2];
    const float* w1   = (const float*)d_in[3];
    const float* b1   = (const float*)d_in[4];
    const float* w2   = (const float*)d_in[5];
    // d_in[6] = attn_b2: softmax-invariant constant shift, a no-op
    const float* lw   = (const float*)d_in[7];
    const float* lb   = (const float*)d_in[8];
    const float* aw   = (const float*)d_in[9];
    const float* lng  = (const float*)d_in[10];
    const float* lnb  = (const float*)d_in[11];

    const size_t CAPN = (size_t)B_ * A_ * H_;
    const size_t GSN  = (size_t)M_ * A_;
    const size_t MKN  = (size_t)B_ * A_;

    float* out_cap = (float*)d_out;
    float* out_gsm;
    float* out_mask;
    if ((size_t)out_size >= CAPN + GSN + MKN) {
        out_gsm  = out_cap + CAPN;
        out_mask = out_cap + CAPN + GSN;
    } else {
        void* p;
        cudaGetSymbolAddress(&p, g_dummy_gates); out_gsm = (float*)p;
        cudaGetSymbolAddress(&p, g_dummy_mask);  out_mask = (float*)p;
    }

    cudaFuncSetAttribute(mma_gemm_kernel<0>, cudaFuncAttributeMaxDynamicSharedMemorySize,
                         SMEM_BYTES);
    cudaFuncSetAttribute(mma_gemm_kernel<1>, cudaFuncAttributeMaxDynamicSharedMemorySize,
                         SMEM_BYTES);

    zero_kernel<<<(M_ + 255) / 256, 256>>>();
    transpose_aw_kernel<<<(A_ * H_ + 255) / 256, 256>>>(aw);

    transpose_w_kernel<<<256, 256>>>(w1);
    mma_gemm_kernel<0><<<dim3(4, 800), 256, SMEM_BYTES>>>(item, pos, b1, w2);
    tma_softmax_kernel<<<B_, 256>>>(seq);

    transpose_w_kernel<<<256, 256>>>(lw);
    mma_gemm_kernel<1><<<dim3(4, 800), 256, SMEM_BYTES>>>(item, nullptr, lb, nullptr);
    ln_kernel<<<M_ / 8, 256>>>(lng, lnb);

    gates_kernel<<<M_ / 8, 256>>>(item, seq, out_gsm);
    mask_kernel<<<(B_ * A_ + 255) / 256, 256>>>(out_mask);

    for (int t = 0; t < 3; t++) {
        cijt_kernel<<<M_ / 8, 256>>>(seq);
        cap_kernel<<<dim3(4, B_), 256>>>(out_cap);
        squash_kernel<<<B_ * A_ / 8, 256>>>(out_cap);
        if (t < 2) bijupd_kernel<<<dim3(4, B_), 256>>>(out_cap);
    }
}